// round 11
// baseline (speedup 1.0000x reference)
#include <cuda_runtime.h>
#include <cuda_fp16.h>
#include <math.h>

#define HB 1024
#define BB 256
#define TD 512
#define GD 4096
#define DEPTH 4
#define ABLK 4096      // halfs per A block (64 rows x 64 k)  = 8KB
#define BBLK 8192      // halfs per B block (128 rows x 64 k) = 16KB
#define ASTG 16384     // A bytes per stage (2 blocks)
#define BSTG 32768     // B bytes per stage (2 blocks)
#define STG  49152     // stage bytes
#define SMEM_DYN (1024 + 1024 + DEPTH * STG)

// ---------------- device state ----------------
__device__ __align__(128) __half g_W1[GD * 1024];            // blocked+swizzled
__device__ __align__(128) __half g_W2[(size_t)GD * 2048];    // blocked+swizzled
__device__ __align__(128) float  g_b1[GD];
__device__ __align__(128) float  g_b2[GD];
__device__ __align__(128) float  g_wih1[GD];
__device__ __align__(128) __half g_A1[2][BB * 1024];         // blocked+swizzled h1
__device__ __align__(128) __half g_A2[2][BB * 2048];         // blocked+swizzled [h1|h2]
__device__ volatile unsigned g_flags[128 * 8];

__host__ __device__ __forceinline__ int swz(int o) { return o ^ ((o >> 3) & 0x70); }

// ---------------- init: permute + block + swizzle weights, reset state ----------------
__global__ void init_k(const float* __restrict__ W_ih1, const float* __restrict__ W_hh1,
                       const float* __restrict__ b_ih1, const float* __restrict__ b_hh1,
                       const float* __restrict__ W_ih2, const float* __restrict__ W_hh2,
                       const float* __restrict__ b_ih2, const float* __restrict__ b_hh2)
{
    int i0 = blockIdx.x * blockDim.x + threadIdx.x;
    int stride = gridDim.x * blockDim.x;
    // permuted gate row n = 4*j + g  <->  original row g*H + j (gate order i,f,g,o)
    for (int i = i0; i < GD * 1024; i += stride) {
        int n = i >> 10, k = i & 1023;
        int orig = (n & 3) * HB + (n >> 2);
        int dst = ((n >> 7) * 16 + (k >> 6)) * BBLK + (swz(((n & 127) << 7) + ((k & 63) << 1)) >> 1);
        g_W1[dst] = __float2half(W_hh1[orig * HB + k]);
    }
    for (size_t i = i0; i < (size_t)GD * 2048; i += stride) {
        int n = (int)(i >> 11), k = (int)(i & 2047);
        int orig = (n & 3) * HB + (n >> 2);
        float v = (k < 1024) ? W_ih2[orig * HB + k] : W_hh2[orig * HB + k - 1024];
        size_t dst = (size_t)((n >> 7) * 32 + (k >> 6)) * BBLK + (swz(((n & 127) << 7) + ((k & 63) << 1)) >> 1);
        g_W2[dst] = __float2half(v);
    }
    for (int i = i0; i < GD; i += stride) {
        int orig = (i & 3) * HB + (i >> 2);
        g_b1[i] = b_ih1[orig] + b_hh1[orig];
        g_b2[i] = b_ih2[orig] + b_hh2[orig];
        g_wih1[i] = W_ih1[orig];
    }
    __half z = __float2half(0.f);
    for (int i = i0; i < 2 * BB * 1024; i += stride) ((__half*)g_A1)[i] = z;
    for (int i = i0; i < 2 * BB * 2048; i += stride) ((__half*)g_A2)[i] = z;
    for (int i = i0; i < 128 * 8; i += stride) g_flags[i] = 0;
}

// ---------------- ptx helpers ----------------
__device__ __forceinline__ unsigned sa(const void* p) {
    unsigned r;
    asm("{ .reg .u64 t; cvta.to.shared.u64 t, %1; cvt.u32.u64 %0, t; }" : "=r"(r) : "l"(p));
    return r;
}
__device__ __forceinline__ void bulk_g2s(unsigned dst, const void* src, unsigned bytes, unsigned mbar) {
    unsigned long long g;
    asm volatile("cvta.to.global.u64 %0, %1;" : "=l"(g) : "l"(src));
    asm volatile("cp.async.bulk.shared::cluster.global.mbarrier::complete_tx::bytes [%0], [%1], %2, [%3];"
                 :: "r"(dst), "l"(g), "r"(bytes), "r"(mbar) : "memory");
}
#define MBAR_INIT(a, c) asm volatile("mbarrier.init.shared.b64 [%0], %1;" :: "r"(a), "r"(c) : "memory")
#define MBAR_EXPECT(a, tx) asm volatile("mbarrier.arrive.expect_tx.shared.b64 _, [%0], %1;" :: "r"(a), "r"(tx) : "memory")
#define MBAR_WAIT(a, par) do {                                                              \
    unsigned _m = (a), _p = (par), _d;                                                      \
    asm volatile("{ .reg .pred p; mbarrier.try_wait.parity.acquire.cta.shared::cta.b64 p, [%1], %2; selp.b32 %0,1,0,p; }" \
        : "=r"(_d) : "r"(_m), "r"(_p) : "memory");                                          \
    if (!_d) asm volatile("{ .reg .pred P; WL_%=: mbarrier.try_wait.parity.acquire.cta.shared::cta.b64 P, [%0], %1, 0x989680; @P bra.uni WD_%=; bra.uni WL_%=; WD_%=: }" \
        :: "r"(_m), "r"(_p) : "memory");                                                    \
} while (0)

__device__ __forceinline__ float sig(float v) { return __fdividef(1.f, 1.f + __expf(-v)); }
__device__ __forceinline__ float tnh(float v) { return __fmaf_rn(2.f, sig(2.f * v), -1.f); }

// distributed flag barrier: one flag store per CTA, 128 parallel spinners
__device__ __forceinline__ void grid_sync(unsigned& epoch) {
    __syncthreads();
    epoch++;
    if (threadIdx.x == 0) {
        __threadfence();
        g_flags[blockIdx.x * 8] = epoch;
    }
    if (threadIdx.x < 128) {
        while (g_flags[threadIdx.x * 8] < epoch) { }
    }
    __threadfence();
    __syncthreads();
}

// ---------------- one layer: K=128 staged GEMM + fused LSTM cell ----------------
// 16 warps: wm=(wid&3)*16 (4 m-groups), wn=(wid>>2)*32 (4 n-groups); warp tile 16x32.
template <int LAYER>
__device__ __forceinline__ void run_layer(
    int t, int par, unsigned sb, unsigned stg0,
    int nt, int mbi, int wid, int lane, int tid, unsigned (&ph)[4],
    const float* __restrict__ x, const float* __restrict__ Wout, float* __restrict__ out,
    float (&cr)[4][2])
{
    const int NP = (LAYER == 1) ? 8 : 16;
    const __half* Ag = (LAYER == 1) ? (g_A1[par] + (size_t)mbi * 16 * ABLK)
                                    : (g_A2[par] + (size_t)mbi * 32 * ABLK);
    const __half* Bg = (LAYER == 1) ? (g_W1 + (size_t)nt * 16 * BBLK)
                                    : (g_W2 + (size_t)nt * 32 * BBLK);
    // next phase's weights (tail prefetch): layer1 -> layer2 (same t); layer2 -> layer1 (t+1)
    const __half* BgN = (LAYER == 1) ? (g_W2 + (size_t)nt * 32 * BBLK)
                                     : (g_W1 + (size_t)nt * 16 * BBLK);
    const float* bias = (LAYER == 1) ? g_b1 : g_b2;

    int wm = (wid & 3) * 16, wn = (wid >> 2) * 32;
    int n0 = nt * 128;
    int odd = lane & 1;

    float acc[4][4];
    #pragma unroll
    for (int b = 0; b < 4; b++)
        #pragma unroll
        for (int c = 0; c < 4; c++) acc[b][c] = 0.f;

    // A-fill for stages 0..3 (their B was prefetched at the previous phase's tail)
    if (tid == 0) {
        #pragma unroll
        for (int u = 0; u < DEPTH; u++) {
            unsigned mA = sb + u * 8;
            MBAR_EXPECT(mA, ASTG);
            bulk_g2s(stg0 + u * STG, Ag + (size_t)(2 * u) * ABLK, ASTG, mA);
        }
    }

    for (int w = 0; w < NP / 4; w++) {
        #pragma unroll
        for (int u = 0; u < DEPTH; u++) {
            int i = w * 4 + u;
            unsigned mA = sb + u * 8, mB = sb + 32 + u * 8;
            MBAR_WAIT(mA, ph[u] & 1);
            MBAR_WAIT(mB, ph[u] & 1);
            ph[u]++;
            unsigned sA = stg0 + u * STG;
            unsigned sB = sA + ASTG;

            #pragma unroll
            for (int ks = 0; ks < 8; ks++) {
                unsigned bA = sA + (ks >> 2) * 8192;
                unsigned bB = sB + (ks >> 2) * 16384;
                int kl = ks & 3;
                unsigned af[4], bf[2][4];
                {
                    int o = ((wm + (lane & 15)) << 7) + kl * 32 + (lane >> 4) * 16;
                    unsigned ad = bA + (unsigned)swz(o);
                    asm volatile("ldmatrix.sync.aligned.m8n8.x4.shared.b16 {%0,%1,%2,%3}, [%4];"
                        : "=r"(af[0]), "=r"(af[1]), "=r"(af[2]), "=r"(af[3]) : "r"(ad));
                }
                int noff = (lane >> 4) * 8 + (lane & 7);
                int kof = ((lane >> 3) & 1) * 16;
                #pragma unroll
                for (int p = 0; p < 2; p++) {
                    int o = ((wn + p * 16 + noff) << 7) + kl * 32 + kof;
                    unsigned ad = bB + (unsigned)swz(o);
                    asm volatile("ldmatrix.sync.aligned.m8n8.x4.shared.b16 {%0,%1,%2,%3}, [%4];"
                        : "=r"(bf[p][0]), "=r"(bf[p][1]), "=r"(bf[p][2]), "=r"(bf[p][3]) : "r"(ad));
                }
                #pragma unroll
                for (int nf = 0; nf < 4; nf++) {
                    unsigned b0 = bf[nf >> 1][(nf & 1) * 2];
                    unsigned b1 = bf[nf >> 1][(nf & 1) * 2 + 1];
                    asm volatile(
                        "mma.sync.aligned.m16n8k16.row.col.f32.f16.f16.f32 "
                        "{%0,%1,%2,%3}, {%4,%5,%6,%7}, {%8,%9}, {%0,%1,%2,%3};"
                        : "+f"(acc[nf][0]), "+f"(acc[nf][1]),
                          "+f"(acc[nf][2]), "+f"(acc[nf][3])
                        : "r"(af[0]), "r"(af[1]), "r"(af[2]), "r"(af[3]),
                          "r"(b0), "r"(b1));
                }
            }
            __syncthreads();
            if (tid == 0) {
                if (i + DEPTH < NP) {
                    MBAR_EXPECT(mA, ASTG);
                    bulk_g2s(sA, Ag + (size_t)(2 * (i + DEPTH)) * ABLK, ASTG, mA);
                    MBAR_EXPECT(mB, BSTG);
                    bulk_g2s(sB, Bg + (size_t)(2 * (i + DEPTH)) * BBLK, BSTG, mB);
                } else {
                    // tail: prefetch NEXT phase's weights for stage u (overlaps epilogue + grid sync)
                    MBAR_EXPECT(mB, BSTG);
                    bulk_g2s(sB, BgN + (size_t)(2 * u) * BBLK, BSTG, mB);
                }
            }
        }
    }

    // ---------------- fused LSTM epilogue ----------------
    // permuted cols: 4j+0=i, 4j+1=f, 4j+2=g, 4j+3=o; xor-1 lane pair exchange
    __half* A1n = g_A1[par ^ 1];
    __half* A2c = g_A2[par];
    __half* A2n = g_A2[par ^ 1];

    {
        int r0 = mbi * 64 + wm + (lane >> 2);
        int r1 = r0 + 8;
        float xv0 = 0.f, xv1 = 0.f;
        if (LAYER == 1) { xv0 = x[r0 * TD + t]; xv1 = x[r1 * TD + t]; }
        float po0 = 0.f, po1 = 0.f;
        #pragma unroll
        for (int nf = 0; nf < 4; nf++) {
            int cb = n0 + wn + nf * 8 + 2 * (lane & 3);
            float v0 = acc[nf][0] + bias[cb];
            float v1 = acc[nf][1] + bias[cb + 1];
            float v2 = acc[nf][2] + bias[cb];
            float v3 = acc[nf][3] + bias[cb + 1];
            if (LAYER == 1) {
                v0 += xv0 * g_wih1[cb];  v1 += xv0 * g_wih1[cb + 1];
                v2 += xv1 * g_wih1[cb];  v3 += xv1 * g_wih1[cb + 1];
            }
            float p0 = __shfl_xor_sync(0xffffffffu, v0, 1);
            float p1 = __shfl_xor_sync(0xffffffffu, v1, 1);
            float p2 = __shfl_xor_sync(0xffffffffu, v2, 1);
            float p3 = __shfl_xor_sync(0xffffffffu, v3, 1);
            if (!odd) {
                int j = cb >> 2;
                float cn0 = sig(v1) * cr[nf][0] + sig(v0) * tnh(p0);
                float h0  = sig(p1) * tnh(cn0);
                cr[nf][0] = cn0;
                float cn1 = sig(v3) * cr[nf][1] + sig(v2) * tnh(p2);
                float h1  = sig(p3) * tnh(cn1);
                cr[nf][1] = cn1;
                __half h0h = __float2half(h0), h1h = __float2half(h1);
                int jc = j >> 6, jl = j & 63;
                int s0 = swz(((r0 & 63) << 7) + (jl << 1)) >> 1;
                int s1 = swz(((r1 & 63) << 7) + (jl << 1)) >> 1;
                if (LAYER == 1) {
                    size_t b1i = (size_t)(mbi * 16 + jc) * ABLK;
                    size_t b2i = (size_t)(mbi * 32 + jc) * ABLK;
                    A1n[b1i + s0] = h0h;  A1n[b1i + s1] = h1h;
                    A2c[b2i + s0] = h0h;  A2c[b2i + s1] = h1h;
                } else {
                    size_t b2i = (size_t)(mbi * 32 + 16 + jc) * ABLK;
                    A2n[b2i + s0] = h0h;  A2n[b2i + s1] = h1h;
                    float w = Wout[j];
                    po0 += h0 * w;  po1 += h1 * w;
                }
            }
        }
        if (LAYER == 2 && !odd) {
            atomicAdd(&out[r0 * TD + t], po0);
            atomicAdd(&out[r1 * TD + t], po1);
        }
    }
}

// ---------------- persistent kernel ----------------
__global__ void __launch_bounds__(512, 1)
lstm_persist(const float* __restrict__ x, const float* __restrict__ Wout,
             const float* __restrict__ bout, float* __restrict__ out)
{
    extern __shared__ unsigned char dynsmem[];
    unsigned sb = (sa(dynsmem) + 1023u) & ~1023u;   // barriers: mbA u*8, mbB 32+u*8
    unsigned stg0 = sb + 1024;

    int tid = threadIdx.x, lane = tid & 31, wid = tid >> 5;
    int cid = blockIdx.x;
    int nt = cid & 31, mbi = cid >> 5;

    if (tid == 0) {
        #pragma unroll
        for (int u = 0; u < DEPTH; u++) { MBAR_INIT(sb + u * 8, 1); MBAR_INIT(sb + 32 + u * 8, 1); }
    }
    asm volatile("fence.proxy.async.shared::cta;" ::: "memory");
    __syncthreads();

    // initial B prefetch: layer1 stages 0..3
    if (tid == 0) {
        const __half* Bg = g_W1 + (size_t)nt * 16 * BBLK;
        #pragma unroll
        for (int u = 0; u < DEPTH; u++) {
            unsigned mB = sb + 32 + u * 8;
            MBAR_EXPECT(mB, BSTG);
            bulk_g2s(stg0 + u * STG + ASTG, Bg + (size_t)(2 * u) * BBLK, BSTG, mB);
        }
    }

    unsigned ph[4] = {0, 0, 0, 0};
    float c1r[4][2], c2r[4][2];
    #pragma unroll
    for (int b = 0; b < 4; b++) { c1r[b][0] = c1r[b][1] = 0.f; c2r[b][0] = c2r[b][1] = 0.f; }

    unsigned epoch = 0;
    float bo = bout[0];

    #pragma unroll 1
    for (int t = 0; t < TD; t++) {
        int par = t & 1;
        if (cid == 0 && tid < 256) out[tid * TD + t] = bo;   // seed with b_out before layer-2 atomics

        run_layer<1>(t, par, sb, stg0, nt, mbi, wid, lane, tid, ph, x, Wout, out, c1r);
        grid_sync(epoch);
        run_layer<2>(t, par, sb, stg0, nt, mbi, wid, lane, tid, ph, x, Wout, out, c2r);
        grid_sync(epoch);
    }
}

// ---------------- launch ----------------
extern "C" void kernel_launch(void* const* d_in, const int* in_sizes, int n_in,
                              void* d_out, int out_size)
{
    const float* x     = (const float*)d_in[0];
    const float* W_ih1 = (const float*)d_in[1];
    const float* W_hh1 = (const float*)d_in[2];
    const float* b_ih1 = (const float*)d_in[3];
    const float* b_hh1 = (const float*)d_in[4];
    const float* W_ih2 = (const float*)d_in[5];
    const float* W_hh2 = (const float*)d_in[6];
    const float* b_ih2 = (const float*)d_in[7];
    const float* b_hh2 = (const float*)d_in[8];
    const float* W_out = (const float*)d_in[9];
    const float* b_out = (const float*)d_in[10];
    float* out = (float*)d_out;

    cudaFuncSetAttribute(lstm_persist, cudaFuncAttributeMaxDynamicSharedMemorySize, SMEM_DYN);

    init_k<<<2048, 256>>>(W_ih1, W_hh1, b_ih1, b_hh1, W_ih2, W_hh2, b_ih2, b_hh2);
    lstm_persist<<<128, 512, SMEM_DYN>>>(x, W_out, b_out, out);

    (void)in_sizes; (void)n_in; (void)out_size;
}

// round 14
// speedup vs baseline: 1.1396x; 1.1396x over previous
#include <cuda_runtime.h>
#include <cuda_fp16.h>
#include <math.h>

#define HB 1024
#define BB 256
#define TD 512
#define GD 4096
#define DEPTH 4
#define ABLK 4096      // halfs per A block (64 rows x 64 k)  = 8KB
#define BBLK 8192      // halfs per B block (128 rows x 64 k) = 16KB
#define ASTG 16384     // A bytes per stage (2 blocks)
#define BSTG 32768     // B bytes per stage (2 blocks)
#define STG  49152     // stage bytes
#define SMEM_DYN (1024 + 1024 + DEPTH * STG)

// ---------------- device state ----------------
__device__ __align__(128) __half g_W1[GD * 1024];            // blocked+swizzled
__device__ __align__(128) __half g_W2[(size_t)GD * 2048];    // blocked+swizzled
__device__ __align__(128) float  g_b1[GD];
__device__ __align__(128) float  g_b2[GD];
__device__ __align__(128) float  g_wih1[GD];
__device__ __align__(128) __half g_A1[2][BB * 1024];         // blocked+swizzled h1
__device__ __align__(128) __half g_A2[2][BB * 2048];         // blocked+swizzled [h1|h2]
__device__ volatile unsigned g_flags[128 * 8];

__host__ __device__ __forceinline__ int swz(int o) { return o ^ ((o >> 3) & 0x70); }

// ---------------- init: permute + block + swizzle weights, reset state ----------------
__global__ void init_k(const float* __restrict__ W_ih1, const float* __restrict__ W_hh1,
                       const float* __restrict__ b_ih1, const float* __restrict__ b_hh1,
                       const float* __restrict__ W_ih2, const float* __restrict__ W_hh2,
                       const float* __restrict__ b_ih2, const float* __restrict__ b_hh2)
{
    int i0 = blockIdx.x * blockDim.x + threadIdx.x;
    int stride = gridDim.x * blockDim.x;
    // permuted gate row n = 4*j + g  <->  original row g*H + j (gate order i,f,g,o)
    for (int i = i0; i < GD * 1024; i += stride) {
        int n = i >> 10, k = i & 1023;
        int orig = (n & 3) * HB + (n >> 2);
        int dst = ((n >> 7) * 16 + (k >> 6)) * BBLK + (swz(((n & 127) << 7) + ((k & 63) << 1)) >> 1);
        g_W1[dst] = __float2half(W_hh1[orig * HB + k]);
    }
    for (size_t i = i0; i < (size_t)GD * 2048; i += stride) {
        int n = (int)(i >> 11), k = (int)(i & 2047);
        int orig = (n & 3) * HB + (n >> 2);
        float v = (k < 1024) ? W_ih2[orig * HB + k] : W_hh2[orig * HB + k - 1024];
        size_t dst = (size_t)((n >> 7) * 32 + (k >> 6)) * BBLK + (swz(((n & 127) << 7) + ((k & 63) << 1)) >> 1);
        g_W2[dst] = __float2half(v);
    }
    for (int i = i0; i < GD; i += stride) {
        int orig = (i & 3) * HB + (i >> 2);
        g_b1[i] = b_ih1[orig] + b_hh1[orig];
        g_b2[i] = b_ih2[orig] + b_hh2[orig];
        g_wih1[i] = W_ih1[orig];
    }
    __half z = __float2half(0.f);
    for (int i = i0; i < 2 * BB * 1024; i += stride) ((__half*)g_A1)[i] = z;
    for (int i = i0; i < 2 * BB * 2048; i += stride) ((__half*)g_A2)[i] = z;
    for (int i = i0; i < 128 * 8; i += stride) g_flags[i] = 0;
}

// ---------------- ptx helpers ----------------
__device__ __forceinline__ unsigned sa(const void* p) {
    unsigned r;
    asm("{ .reg .u64 t; cvta.to.shared.u64 t, %1; cvt.u32.u64 %0, t; }" : "=r"(r) : "l"(p));
    return r;
}
__device__ __forceinline__ void bulk_g2s(unsigned dst, const void* src, unsigned bytes, unsigned mbar) {
    unsigned long long g;
    asm volatile("cvta.to.global.u64 %0, %1;" : "=l"(g) : "l"(src));
    asm volatile("cp.async.bulk.shared::cluster.global.mbarrier::complete_tx::bytes [%0], [%1], %2, [%3];"
                 :: "r"(dst), "l"(g), "r"(bytes), "r"(mbar) : "memory");
}
#define MBAR_INIT(a, c) asm volatile("mbarrier.init.shared.b64 [%0], %1;" :: "r"(a), "r"(c) : "memory")
// arriving expect (the ONE arrive of each phase)
#define MBAR_ARRIVE_EXPECT(a, tx) \
    asm volatile("mbarrier.arrive.expect_tx.shared.b64 _, [%0], %1;" :: "r"(a), "r"(tx) : "memory")
// non-arriving expect (adds tx bytes to the current phase; must precede its copy)
#define MBAR_EXPECT_ONLY(a, tx) \
    asm volatile("mbarrier.expect_tx.relaxed.cta.shared::cta.b64 [%0], %1;" :: "r"(a), "r"(tx) : "memory")
#define MBAR_WAIT(a, par) do {                                                              \
    unsigned _m = (a), _p = (par), _d;                                                      \
    asm volatile("{ .reg .pred p; mbarrier.try_wait.parity.acquire.cta.shared::cta.b64 p, [%1], %2; selp.b32 %0,1,0,p; }" \
        : "=r"(_d) : "r"(_m), "r"(_p) : "memory");                                          \
    if (!_d) asm volatile("{ .reg .pred P; WL_%=: mbarrier.try_wait.parity.acquire.cta.shared::cta.b64 P, [%0], %1, 0x989680; @P bra.uni WD_%=; bra.uni WL_%=; WD_%=: }" \
        :: "r"(_m), "r"(_p) : "memory");                                                    \
} while (0)

__device__ __forceinline__ float sig(float v) { return __fdividef(1.f, 1.f + __expf(-v)); }
__device__ __forceinline__ float tnh(float v) { return __fmaf_rn(2.f, sig(2.f * v), -1.f); }

// distributed flag barrier: one flag store per CTA, 128 parallel spinners
__device__ __forceinline__ void grid_sync(unsigned& epoch) {
    __syncthreads();
    epoch++;
    if (threadIdx.x == 0) {
        __threadfence();
        g_flags[blockIdx.x * 8] = epoch;
    }
    if (threadIdx.x < 128) {
        while (g_flags[threadIdx.x * 8] < epoch) { }
    }
    __threadfence();
    __syncthreads();
}

// ---------------- one layer: K=128 staged GEMM + fused LSTM cell ----------------
// 8 warps: wm=(wid&1)*32 (2 m-groups), wn=(wid>>1)*32 (4 n-groups); warp tile 32x32.
// ONE mbarrier per stage: A refills arrive.expect; B prefetches expect-only (before copy).
template <int LAYER>
__device__ __forceinline__ void run_layer(
    int t, int par, unsigned sb, unsigned stg0,
    int nt, int mbi, int wid, int lane, int tid, unsigned (&ph)[4],
    const float* __restrict__ x, const float* __restrict__ Wout, float* __restrict__ out,
    float (&cr)[2][4][2])
{
    const int NP = (LAYER == 1) ? 8 : 16;
    const __half* Ag = (LAYER == 1) ? (g_A1[par] + (size_t)mbi * 16 * ABLK)
                                    : (g_A2[par] + (size_t)mbi * 32 * ABLK);
    const __half* Bg = (LAYER == 1) ? (g_W1 + (size_t)nt * 16 * BBLK)
                                    : (g_W2 + (size_t)nt * 32 * BBLK);
    // next phase's weights (tail prefetch): layer1 -> layer2 (same t); layer2 -> layer1 (t+1)
    const __half* BgN = (LAYER == 1) ? (g_W2 + (size_t)nt * 32 * BBLK)
                                     : (g_W1 + (size_t)nt * 16 * BBLK);
    const float* bias = (LAYER == 1) ? g_b1 : g_b2;

    int wm = (wid & 1) * 32, wn = (wid >> 1) * 32;
    int n0 = nt * 128;
    int odd = lane & 1;

    float acc[2][4][4];
    #pragma unroll
    for (int a = 0; a < 2; a++)
        #pragma unroll
        for (int b = 0; b < 4; b++)
            #pragma unroll
            for (int c = 0; c < 4; c++) acc[a][b][c] = 0.f;

    // layer start: A-fill for stages 0..3 (their B was prefetched at the previous phase's
    // tail with an expect-only). This arrive.expect is the single arrive of the phase.
    if (tid == 0) {
        #pragma unroll
        for (int u = 0; u < DEPTH; u++) {
            unsigned mb = sb + u * 8;
            MBAR_ARRIVE_EXPECT(mb, ASTG);
            bulk_g2s(stg0 + u * STG, Ag + (size_t)(2 * u) * ABLK, ASTG, mb);
        }
    }

    // fragment loader for one k16 slice (ks = 0..7 within the 128-K stage)
    auto ldsmAB = [&](int ks, unsigned sA, unsigned sB,
                      unsigned (&af)[2][4], unsigned (&bf)[2][4]) {
        unsigned bA = sA + (ks >> 2) * 8192;
        unsigned bB = sB + (ks >> 2) * 16384;
        int kl = ks & 3;
        #pragma unroll
        for (int mf = 0; mf < 2; mf++) {
            int o = ((wm + mf * 16 + (lane & 15)) << 7) + kl * 32 + (lane >> 4) * 16;
            unsigned ad = bA + (unsigned)swz(o);
            asm volatile("ldmatrix.sync.aligned.m8n8.x4.shared.b16 {%0,%1,%2,%3}, [%4];"
                : "=r"(af[mf][0]), "=r"(af[mf][1]), "=r"(af[mf][2]), "=r"(af[mf][3]) : "r"(ad));
        }
        int noff = (lane >> 4) * 8 + (lane & 7);
        int kof = ((lane >> 3) & 1) * 16;
        #pragma unroll
        for (int p = 0; p < 2; p++) {
            int o = ((wn + p * 16 + noff) << 7) + kl * 32 + kof;
            unsigned ad = bB + (unsigned)swz(o);
            asm volatile("ldmatrix.sync.aligned.m8n8.x4.shared.b16 {%0,%1,%2,%3}, [%4];"
                : "=r"(bf[p][0]), "=r"(bf[p][1]), "=r"(bf[p][2]), "=r"(bf[p][3]) : "r"(ad));
        }
    };

    for (int w = 0; w < NP / 4; w++) {
        #pragma unroll
        for (int u = 0; u < DEPTH; u++) {
            int i = w * 4 + u;
            unsigned mb = sb + u * 8;
            MBAR_WAIT(mb, ph[u] & 1);
            ph[u]++;
            unsigned sA = stg0 + u * STG;
            unsigned sB = sA + ASTG;

            // double-buffered fragments: prefetch slice ks+1 before slice ks's MMAs
            unsigned af[2][2][4], bf[2][2][4];
            ldsmAB(0, sA, sB, af[0], bf[0]);
            #pragma unroll
            for (int ks = 0; ks < 8; ks++) {
                int cur = ks & 1;
                if (ks < 7) ldsmAB(ks + 1, sA, sB, af[cur ^ 1], bf[cur ^ 1]);
                #pragma unroll
                for (int mf = 0; mf < 2; mf++)
                    #pragma unroll
                    for (int nf = 0; nf < 4; nf++) {
                        unsigned b0 = bf[cur][nf >> 1][(nf & 1) * 2];
                        unsigned b1 = bf[cur][nf >> 1][(nf & 1) * 2 + 1];
                        asm volatile(
                            "mma.sync.aligned.m16n8k16.row.col.f32.f16.f16.f32 "
                            "{%0,%1,%2,%3}, {%4,%5,%6,%7}, {%8,%9}, {%0,%1,%2,%3};"
                            : "+f"(acc[mf][nf][0]), "+f"(acc[mf][nf][1]),
                              "+f"(acc[mf][nf][2]), "+f"(acc[mf][nf][3])
                            : "r"(af[cur][mf][0]), "r"(af[cur][mf][1]),
                              "r"(af[cur][mf][2]), "r"(af[cur][mf][3]),
                              "r"(b0), "r"(b1));
                    }
            }
            __syncthreads();
            if (tid == 0) {
                if (i + DEPTH < NP) {
                    // inner refill: one arrive.expect for A+B of the next phase
                    MBAR_ARRIVE_EXPECT(mb, ASTG + BSTG);
                    bulk_g2s(sA, Ag + (size_t)(2 * (i + DEPTH)) * ABLK, ASTG, mb);
                    bulk_g2s(sB, Bg + (size_t)(2 * (i + DEPTH)) * BBLK, BSTG, mb);
                } else {
                    // tail: expect-only + next phase's B (its arrive comes at next layer start)
                    MBAR_EXPECT_ONLY(mb, BSTG);
                    bulk_g2s(sB, BgN + (size_t)(2 * u) * BBLK, BSTG, mb);
                }
            }
        }
    }

    // ---------------- fused LSTM epilogue (validated) ----------------
    // permuted cols: 4j+0=i, 4j+1=f, 4j+2=g, 4j+3=o; xor-1 lane pair exchange
    __half* A1n = g_A1[par ^ 1];
    __half* A2c = g_A2[par];
    __half* A2n = g_A2[par ^ 1];

    #pragma unroll
    for (int mf = 0; mf < 2; mf++) {
        int r0 = mbi * 64 + wm + mf * 16 + (lane >> 2);
        int r1 = r0 + 8;
        float xv0 = 0.f, xv1 = 0.f;
        if (LAYER == 1) { xv0 = x[r0 * TD + t]; xv1 = x[r1 * TD + t]; }
        float po0 = 0.f, po1 = 0.f;
        #pragma unroll
        for (int nf = 0; nf < 4; nf++) {
            int cb = n0 + wn + nf * 8 + 2 * (lane & 3);
            float v0 = acc[mf][nf][0] + bias[cb];
            float v1 = acc[mf][nf][1] + bias[cb + 1];
            float v2 = acc[mf][nf][2] + bias[cb];
            float v3 = acc[mf][nf][3] + bias[cb + 1];
            if (LAYER == 1) {
                v0 += xv0 * g_wih1[cb];  v1 += xv0 * g_wih1[cb + 1];
                v2 += xv1 * g_wih1[cb];  v3 += xv1 * g_wih1[cb + 1];
            }
            float p0 = __shfl_xor_sync(0xffffffffu, v0, 1);
            float p1 = __shfl_xor_sync(0xffffffffu, v1, 1);
            float p2 = __shfl_xor_sync(0xffffffffu, v2, 1);
            float p3 = __shfl_xor_sync(0xffffffffu, v3, 1);
            if (!odd) {
                int j = cb >> 2;
                float cn0 = sig(v1) * cr[mf][nf][0] + sig(v0) * tnh(p0);
                float h0  = sig(p1) * tnh(cn0);
                cr[mf][nf][0] = cn0;
                float cn1 = sig(v3) * cr[mf][nf][1] + sig(v2) * tnh(p2);
                float h1  = sig(p3) * tnh(cn1);
                cr[mf][nf][1] = cn1;
                __half h0h = __float2half(h0), h1h = __float2half(h1);
                int jc = j >> 6, jl = j & 63;
                int s0 = swz(((r0 & 63) << 7) + (jl << 1)) >> 1;
                int s1 = swz(((r1 & 63) << 7) + (jl << 1)) >> 1;
                if (LAYER == 1) {
                    size_t b1i = (size_t)(mbi * 16 + jc) * ABLK;
                    size_t b2i = (size_t)(mbi * 32 + jc) * ABLK;
                    A1n[b1i + s0] = h0h;  A1n[b1i + s1] = h1h;
                    A2c[b2i + s0] = h0h;  A2c[b2i + s1] = h1h;
                } else {
                    size_t b2i = (size_t)(mbi * 32 + 16 + jc) * ABLK;
                    A2n[b2i + s0] = h0h;  A2n[b2i + s1] = h1h;
                    float w = Wout[j];
                    po0 += h0 * w;  po1 += h1 * w;
                }
            }
        }
        if (LAYER == 2 && !odd) {
            atomicAdd(&out[r0 * TD + t], po0);
            atomicAdd(&out[r1 * TD + t], po1);
        }
    }
}

// ---------------- persistent kernel ----------------
__global__ void __launch_bounds__(256, 1)
lstm_persist(const float* __restrict__ x, const float* __restrict__ Wout,
             const float* __restrict__ bout, float* __restrict__ out)
{
    extern __shared__ unsigned char dynsmem[];
    unsigned sb = (sa(dynsmem) + 1023u) & ~1023u;   // barriers: mb[u] = sb + u*8
    unsigned stg0 = sb + 1024;

    int tid = threadIdx.x, lane = tid & 31, wid = tid >> 5;
    int cid = blockIdx.x;
    int nt = cid & 31, mbi = cid >> 5;

    if (tid == 0) {
        #pragma unroll
        for (int u = 0; u < DEPTH; u++) MBAR_INIT(sb + u * 8, 1);
    }
    asm volatile("fence.proxy.async.shared::cta;" ::: "memory");
    __syncthreads();

    // initial B prefetch: layer1 stages 0..3 (expect-only; arrive comes at layer-1 start)
    if (tid == 0) {
        const __half* Bg = g_W1 + (size_t)nt * 16 * BBLK;
        #pragma unroll
        for (int u = 0; u < DEPTH; u++) {
            unsigned mb = sb + u * 8;
            MBAR_EXPECT_ONLY(mb, BSTG);
            bulk_g2s(stg0 + u * STG + ASTG, Bg + (size_t)(2 * u) * BBLK, BSTG, mb);
        }
    }

    unsigned ph[4] = {0, 0, 0, 0};
    float c1r[2][4][2], c2r[2][4][2];
    #pragma unroll
    for (int a = 0; a < 2; a++)
        #pragma unroll
        for (int b = 0; b < 4; b++) { c1r[a][b][0] = c1r[a][b][1] = 0.f; c2r[a][b][0] = c2r[a][b][1] = 0.f; }

    unsigned epoch = 0;
    float bo = bout[0];

    #pragma unroll 1
    for (int t = 0; t < TD; t++) {
        int par = t & 1;
        if (cid == 0) out[tid * TD + t] = bo;   // seed with b_out before layer-2 atomics

        run_layer<1>(t, par, sb, stg0, nt, mbi, wid, lane, tid, ph, x, Wout, out, c1r);
        grid_sync(epoch);
        run_layer<2>(t, par, sb, stg0, nt, mbi, wid, lane, tid, ph, x, Wout, out, c2r);
        grid_sync(epoch);
    }
}

// ---------------- launch ----------------
extern "C" void kernel_launch(void* const* d_in, const int* in_sizes, int n_in,
                              void* d_out, int out_size)
{
    const float* x     = (const float*)d_in[0];
    const float* W_ih1 = (const float*)d_in[1];
    const float* W_hh1 = (const float*)d_in[2];
    const float* b_ih1 = (const float*)d_in[3];
    const float* b_hh1 = (const float*)d_in[4];
    const float* W_ih2 = (const float*)d_in[5];
    const float* W_hh2 = (const float*)d_in[6];
    const float* b_ih2 = (const float*)d_in[7];
    const float* b_hh2 = (const float*)d_in[8];
    const float* W_out = (const float*)d_in[9];
    const float* b_out = (const float*)d_in[10];
    float* out = (float*)d_out;

    cudaFuncSetAttribute(lstm_persist, cudaFuncAttributeMaxDynamicSharedMemorySize, SMEM_DYN);

    init_k<<<2048, 256>>>(W_ih1, W_hh1, b_ih1, b_hh1, W_ih2, W_hh2, b_ih2, b_hh2);
    lstm_persist<<<128, 256, SMEM_DYN>>>(x, W_out, b_out, out);

    (void)in_sizes; (void)n_in; (void)out_size;
}

// round 15
// speedup vs baseline: 1.3062x; 1.1462x over previous
#include <cuda_runtime.h>
#include <cuda_fp16.h>
#include <math.h>

#define HB 1024
#define BB 256
#define TD 512
#define GD 4096
#define DEPTH 4
#define ABLK 4096      // halfs per A block (64 rows x 64 k)  = 8KB
#define BBLK 8192      // halfs per B block (128 rows x 64 k) = 16KB
#define ASTG 16384     // A bytes per stage (2 blocks)
#define BSTG 32768     // B bytes per stage (2 blocks)
#define STG  49152     // stage bytes
#define SMEM_DYN (1024 + 1024 + DEPTH * STG)

// ---------------- device state ----------------
__device__ __align__(128) __half g_W1[GD * 1024];            // blocked+swizzled
__device__ __align__(128) __half g_W2[(size_t)GD * 2048];    // blocked+swizzled
__device__ __align__(128) float  g_b1[GD];
__device__ __align__(128) float  g_b2[GD];
__device__ __align__(128) float  g_wih1[GD];
__device__ __align__(128) __half g_A1[2][BB * 1024];         // blocked+swizzled h1
__device__ __align__(128) __half g_A2[2][BB * 2048];         // blocked+swizzled [h1|h2]
__device__ volatile unsigned g_flags[128 * 8];

__host__ __device__ __forceinline__ int swz(int o) { return o ^ ((o >> 3) & 0x70); }

// ---------------- init: permute + block + swizzle weights, reset state ----------------
__global__ void init_k(const float* __restrict__ W_ih1, const float* __restrict__ W_hh1,
                       const float* __restrict__ b_ih1, const float* __restrict__ b_hh1,
                       const float* __restrict__ W_ih2, const float* __restrict__ W_hh2,
                       const float* __restrict__ b_ih2, const float* __restrict__ b_hh2)
{
    int i0 = blockIdx.x * blockDim.x + threadIdx.x;
    int stride = gridDim.x * blockDim.x;
    // permuted gate row n = 4*j + g  <->  original row g*H + j (gate order i,f,g,o)
    for (int i = i0; i < GD * 1024; i += stride) {
        int n = i >> 10, k = i & 1023;
        int orig = (n & 3) * HB + (n >> 2);
        int dst = ((n >> 7) * 16 + (k >> 6)) * BBLK + (swz(((n & 127) << 7) + ((k & 63) << 1)) >> 1);
        g_W1[dst] = __float2half(W_hh1[orig * HB + k]);
    }
    for (size_t i = i0; i < (size_t)GD * 2048; i += stride) {
        int n = (int)(i >> 11), k = (int)(i & 2047);
        int orig = (n & 3) * HB + (n >> 2);
        float v = (k < 1024) ? W_ih2[orig * HB + k] : W_hh2[orig * HB + k - 1024];
        size_t dst = (size_t)((n >> 7) * 32 + (k >> 6)) * BBLK + (swz(((n & 127) << 7) + ((k & 63) << 1)) >> 1);
        g_W2[dst] = __float2half(v);
    }
    for (int i = i0; i < GD; i += stride) {
        int orig = (i & 3) * HB + (i >> 2);
        g_b1[i] = b_ih1[orig] + b_hh1[orig];
        g_b2[i] = b_ih2[orig] + b_hh2[orig];
        g_wih1[i] = W_ih1[orig];
    }
    __half z = __float2half(0.f);
    for (int i = i0; i < 2 * BB * 1024; i += stride) ((__half*)g_A1)[i] = z;
    for (int i = i0; i < 2 * BB * 2048; i += stride) ((__half*)g_A2)[i] = z;
    for (int i = i0; i < 128 * 8; i += stride) g_flags[i] = 0;
}

// ---------------- ptx helpers ----------------
__device__ __forceinline__ unsigned sa(const void* p) {
    unsigned r;
    asm("{ .reg .u64 t; cvta.to.shared.u64 t, %1; cvt.u32.u64 %0, t; }" : "=r"(r) : "l"(p));
    return r;
}
__device__ __forceinline__ void bulk_g2s(unsigned dst, const void* src, unsigned bytes, unsigned mbar) {
    unsigned long long g;
    asm volatile("cvta.to.global.u64 %0, %1;" : "=l"(g) : "l"(src));
    asm volatile("cp.async.bulk.shared::cluster.global.mbarrier::complete_tx::bytes [%0], [%1], %2, [%3];"
                 :: "r"(dst), "l"(g), "r"(bytes), "r"(mbar) : "memory");
}
#define MBAR_INIT(a, c) asm volatile("mbarrier.init.shared.b64 [%0], %1;" :: "r"(a), "r"(c) : "memory")
// arriving expect (the ONE arrive of each phase)
#define MBAR_ARRIVE_EXPECT(a, tx) \
    asm volatile("mbarrier.arrive.expect_tx.shared.b64 _, [%0], %1;" :: "r"(a), "r"(tx) : "memory")
// non-arriving expect (adds tx bytes to the current phase; must precede its copy)
#define MBAR_EXPECT_ONLY(a, tx) \
    asm volatile("mbarrier.expect_tx.relaxed.cta.shared::cta.b64 [%0], %1;" :: "r"(a), "r"(tx) : "memory")
#define MBAR_WAIT(a, par) do {                                                              \
    unsigned _m = (a), _p = (par), _d;                                                      \
    asm volatile("{ .reg .pred p; mbarrier.try_wait.parity.acquire.cta.shared::cta.b64 p, [%1], %2; selp.b32 %0,1,0,p; }" \
        : "=r"(_d) : "r"(_m), "r"(_p) : "memory");                                          \
    if (!_d) asm volatile("{ .reg .pred P; WL_%=: mbarrier.try_wait.parity.acquire.cta.shared::cta.b64 P, [%0], %1, 0x989680; @P bra.uni WD_%=; bra.uni WL_%=; WD_%=: }" \
        :: "r"(_m), "r"(_p) : "memory");                                                    \
} while (0)

__device__ __forceinline__ float sig(float v) { return __fdividef(1.f, 1.f + __expf(-v)); }
__device__ __forceinline__ float tnh(float v) { return __fmaf_rn(2.f, sig(2.f * v), -1.f); }

// distributed flag barrier: one flag store per CTA, 128 parallel spinners
__device__ __forceinline__ void grid_sync(unsigned& epoch) {
    __syncthreads();
    epoch++;
    if (threadIdx.x == 0) {
        __threadfence();
        g_flags[blockIdx.x * 8] = epoch;
    }
    if (threadIdx.x < 128) {
        while (g_flags[threadIdx.x * 8] < epoch) { }
    }
    __threadfence();
    __syncthreads();
}

// ---------------- one layer: K=128 staged GEMM + fused LSTM cell ----------------
// 8 warps: wm=(wid&1)*32, wn=(wid>>1)*32; warp tile 32x32. One mbarrier per stage.
// tail_mode: 0 = expect-only + B-of-next (L1 -> L2, A not globally ready until sync)
//            1 = FULL arrive.expect + A+B of next phase (L2 -> L1(t+1), h1 globally ready)
//            2 = none (final L2)
// LAYER==2 issues a start A-fill (arrive.expect ASTG) pairing with mode-0 tails.
// LAYER==1 issues nothing at start: its stages were fully filled by the previous
// L2's mode-1 tail (or the kernel prologue for t=0).
template <int LAYER>
__device__ __forceinline__ void run_layer(
    int t, int par, unsigned sb, unsigned stg0,
    int nt, int mbi, int wid, int lane, int tid, unsigned (&ph)[4],
    int tail_mode,
    const float* __restrict__ x, const float* __restrict__ Wout, float* __restrict__ out,
    float (&cr)[2][4][2])
{
    const int NP = (LAYER == 1) ? 8 : 16;
    const __half* Ag = (LAYER == 1) ? (g_A1[par] + (size_t)mbi * 16 * ABLK)
                                    : (g_A2[par] + (size_t)mbi * 32 * ABLK);
    const __half* Bg = (LAYER == 1) ? (g_W1 + (size_t)nt * 16 * BBLK)
                                    : (g_W2 + (size_t)nt * 32 * BBLK);
    // tail targets: L1 -> L2's weights; L2 -> L1(t+1)'s activations + weights
    const __half* AgT = (LAYER == 1) ? (const __half*)0
                                     : (g_A1[par ^ 1] + (size_t)mbi * 16 * ABLK);
    const __half* BgT = (LAYER == 1) ? (g_W2 + (size_t)nt * 32 * BBLK)
                                     : (g_W1 + (size_t)nt * 16 * BBLK);
    const float* bias = (LAYER == 1) ? g_b1 : g_b2;

    int wm = (wid & 1) * 32, wn = (wid >> 1) * 32;
    int n0 = nt * 128;
    int odd = lane & 1;

    float acc[2][4][4];
    #pragma unroll
    for (int a = 0; a < 2; a++)
        #pragma unroll
        for (int b = 0; b < 4; b++)
            #pragma unroll
            for (int c = 0; c < 4; c++) acc[a][b][c] = 0.f;

    // L2 start: A-fill completes the phase opened by L1's expect-only-B tail
    if (LAYER == 2 && tid == 0) {
        #pragma unroll
        for (int u = 0; u < DEPTH; u++) {
            unsigned mb = sb + u * 8;
            MBAR_ARRIVE_EXPECT(mb, ASTG);
            bulk_g2s(stg0 + u * STG, Ag + (size_t)(2 * u) * ABLK, ASTG, mb);
        }
    }

    // fragment loader for one k16 slice (ks = 0..7 within the 128-K stage)
    auto ldsmAB = [&](int ks, unsigned sA, unsigned sB,
                      unsigned (&af)[2][4], unsigned (&bf)[2][4]) {
        unsigned bA = sA + (ks >> 2) * 8192;
        unsigned bB = sB + (ks >> 2) * 16384;
        int kl = ks & 3;
        #pragma unroll
        for (int mf = 0; mf < 2; mf++) {
            int o = ((wm + mf * 16 + (lane & 15)) << 7) + kl * 32 + (lane >> 4) * 16;
            unsigned ad = bA + (unsigned)swz(o);
            asm volatile("ldmatrix.sync.aligned.m8n8.x4.shared.b16 {%0,%1,%2,%3}, [%4];"
                : "=r"(af[mf][0]), "=r"(af[mf][1]), "=r"(af[mf][2]), "=r"(af[mf][3]) : "r"(ad));
        }
        int noff = (lane >> 4) * 8 + (lane & 7);
        int kof = ((lane >> 3) & 1) * 16;
        #pragma unroll
        for (int p = 0; p < 2; p++) {
            int o = ((wn + p * 16 + noff) << 7) + kl * 32 + kof;
            unsigned ad = bB + (unsigned)swz(o);
            asm volatile("ldmatrix.sync.aligned.m8n8.x4.shared.b16 {%0,%1,%2,%3}, [%4];"
                : "=r"(bf[p][0]), "=r"(bf[p][1]), "=r"(bf[p][2]), "=r"(bf[p][3]) : "r"(ad));
        }
    };

    for (int w = 0; w < NP / 4; w++) {
        #pragma unroll
        for (int u = 0; u < DEPTH; u++) {
            int i = w * 4 + u;
            unsigned mb = sb + u * 8;
            MBAR_WAIT(mb, ph[u] & 1);
            ph[u]++;
            unsigned sA = stg0 + u * STG;
            unsigned sB = sA + ASTG;

            // double-buffered fragments: prefetch slice ks+1 before slice ks's MMAs
            unsigned af[2][2][4], bf[2][2][4];
            ldsmAB(0, sA, sB, af[0], bf[0]);
            #pragma unroll
            for (int ks = 0; ks < 8; ks++) {
                int cur = ks & 1;
                if (ks < 7) ldsmAB(ks + 1, sA, sB, af[cur ^ 1], bf[cur ^ 1]);
                #pragma unroll
                for (int mf = 0; mf < 2; mf++)
                    #pragma unroll
                    for (int nf = 0; nf < 4; nf++) {
                        unsigned b0 = bf[cur][nf >> 1][(nf & 1) * 2];
                        unsigned b1 = bf[cur][nf >> 1][(nf & 1) * 2 + 1];
                        asm volatile(
                            "mma.sync.aligned.m16n8k16.row.col.f32.f16.f16.f32 "
                            "{%0,%1,%2,%3}, {%4,%5,%6,%7}, {%8,%9}, {%0,%1,%2,%3};"
                            : "+f"(acc[mf][nf][0]), "+f"(acc[mf][nf][1]),
                              "+f"(acc[mf][nf][2]), "+f"(acc[mf][nf][3])
                            : "r"(af[cur][mf][0]), "r"(af[cur][mf][1]),
                              "r"(af[cur][mf][2]), "r"(af[cur][mf][3]),
                              "r"(b0), "r"(b1));
                    }
            }
            __syncthreads();
            if (tid == 0) {
                if (i + DEPTH < NP) {
                    // inner refill: one arrive.expect for A+B of the next phase
                    MBAR_ARRIVE_EXPECT(mb, ASTG + BSTG);
                    bulk_g2s(sA, Ag + (size_t)(2 * (i + DEPTH)) * ABLK, ASTG, mb);
                    bulk_g2s(sB, Bg + (size_t)(2 * (i + DEPTH)) * BBLK, BSTG, mb);
                } else if (tail_mode == 0) {
                    // L1 tail: expect-only + next layer's weights (arrive at L2 start)
                    MBAR_EXPECT_ONLY(mb, BSTG);
                    bulk_g2s(sB, BgT + (size_t)(2 * u) * BBLK, BSTG, mb);
                } else if (tail_mode == 1) {
                    // L2 tail: FULL fill of L1(t+1)'s stage u — h1(t) globally complete
                    MBAR_ARRIVE_EXPECT(mb, ASTG + BSTG);
                    bulk_g2s(sA, AgT + (size_t)(2 * u) * ABLK, ASTG, mb);
                    bulk_g2s(sB, BgT + (size_t)(2 * u) * BBLK, BSTG, mb);
                }
                // tail_mode == 2: nothing (final step)
            }
        }
    }

    // ---------------- fused LSTM epilogue (validated) ----------------
    // permuted cols: 4j+0=i, 4j+1=f, 4j+2=g, 4j+3=o; xor-1 lane pair exchange
    __half* A1n = g_A1[par ^ 1];
    __half* A2c = g_A2[par];
    __half* A2n = g_A2[par ^ 1];

    #pragma unroll
    for (int mf = 0; mf < 2; mf++) {
        int r0 = mbi * 64 + wm + mf * 16 + (lane >> 2);
        int r1 = r0 + 8;
        float xv0 = 0.f, xv1 = 0.f;
        if (LAYER == 1) { xv0 = x[r0 * TD + t]; xv1 = x[r1 * TD + t]; }
        float po0 = 0.f, po1 = 0.f;
        #pragma unroll
        for (int nf = 0; nf < 4; nf++) {
            int cb = n0 + wn + nf * 8 + 2 * (lane & 3);
            float v0 = acc[mf][nf][0] + bias[cb];
            float v1 = acc[mf][nf][1] + bias[cb + 1];
            float v2 = acc[mf][nf][2] + bias[cb];
            float v3 = acc[mf][nf][3] + bias[cb + 1];
            if (LAYER == 1) {
                v0 += xv0 * g_wih1[cb];  v1 += xv0 * g_wih1[cb + 1];
                v2 += xv1 * g_wih1[cb];  v3 += xv1 * g_wih1[cb + 1];
            }
            float p0 = __shfl_xor_sync(0xffffffffu, v0, 1);
            float p1 = __shfl_xor_sync(0xffffffffu, v1, 1);
            float p2 = __shfl_xor_sync(0xffffffffu, v2, 1);
            float p3 = __shfl_xor_sync(0xffffffffu, v3, 1);
            if (!odd) {
                int j = cb >> 2;
                float cn0 = sig(v1) * cr[mf][nf][0] + sig(v0) * tnh(p0);
                float h0  = sig(p1) * tnh(cn0);
                cr[mf][nf][0] = cn0;
                float cn1 = sig(v3) * cr[mf][nf][1] + sig(v2) * tnh(p2);
                float h1  = sig(p3) * tnh(cn1);
                cr[mf][nf][1] = cn1;
                __half h0h = __float2half(h0), h1h = __float2half(h1);
                int jc = j >> 6, jl = j & 63;
                int s0 = swz(((r0 & 63) << 7) + (jl << 1)) >> 1;
                int s1 = swz(((r1 & 63) << 7) + (jl << 1)) >> 1;
                if (LAYER == 1) {
                    size_t b1i = (size_t)(mbi * 16 + jc) * ABLK;
                    size_t b2i = (size_t)(mbi * 32 + jc) * ABLK;
                    A1n[b1i + s0] = h0h;  A1n[b1i + s1] = h1h;
                    A2c[b2i + s0] = h0h;  A2c[b2i + s1] = h1h;
                } else {
                    size_t b2i = (size_t)(mbi * 32 + 16 + jc) * ABLK;
                    A2n[b2i + s0] = h0h;  A2n[b2i + s1] = h1h;
                    float w = Wout[j];
                    po0 += h0 * w;  po1 += h1 * w;
                }
            }
        }
        if (LAYER == 2 && !odd) {
            atomicAdd(&out[r0 * TD + t], po0);
            atomicAdd(&out[r1 * TD + t], po1);
        }
    }
}

// ---------------- persistent kernel ----------------
__global__ void __launch_bounds__(256, 1)
lstm_persist(const float* __restrict__ x, const float* __restrict__ Wout,
             const float* __restrict__ bout, float* __restrict__ out)
{
    extern __shared__ unsigned char dynsmem[];
    unsigned sb = (sa(dynsmem) + 1023u) & ~1023u;   // barriers: mb[u] = sb + u*8
    unsigned stg0 = sb + 1024;

    int tid = threadIdx.x, lane = tid & 31, wid = tid >> 5;
    int cid = blockIdx.x;
    int nt = cid & 31, mbi = cid >> 5;

    if (tid == 0) {
        #pragma unroll
        for (int u = 0; u < DEPTH; u++) MBAR_INIT(sb + u * 8, 1);
    }
    asm volatile("fence.proxy.async.shared::cta;" ::: "memory");
    __syncthreads();

    // prologue: FULL fill of L1(t=0)'s stages 0..3 (A1[0] zeros + W1), full arrive
    if (tid == 0) {
        const __half* Ag = g_A1[0] + (size_t)mbi * 16 * ABLK;
        const __half* Bg = g_W1 + (size_t)nt * 16 * BBLK;
        #pragma unroll
        for (int u = 0; u < DEPTH; u++) {
            unsigned mb = sb + u * 8;
            MBAR_ARRIVE_EXPECT(mb, ASTG + BSTG);
            bulk_g2s(stg0 + u * STG, Ag + (size_t)(2 * u) * ABLK, ASTG, mb);
            bulk_g2s(stg0 + u * STG + ASTG, Bg + (size_t)(2 * u) * BBLK, BSTG, mb);
        }
    }

    unsigned ph[4] = {0, 0, 0, 0};
    float c1r[2][4][2], c2r[2][4][2];
    #pragma unroll
    for (int a = 0; a < 2; a++)
        #pragma unroll
        for (int b = 0; b < 4; b++) { c1r[a][b][0] = c1r[a][b][1] = 0.f; c2r[a][b][0] = c2r[a][b][1] = 0.f; }

    unsigned epoch = 0;
    float bo = bout[0];

    #pragma unroll 1
    for (int t = 0; t < TD; t++) {
        int par = t & 1;
        if (cid == 0) out[tid * TD + t] = bo;   // seed with b_out before layer-2 atomics

        run_layer<1>(t, par, sb, stg0, nt, mbi, wid, lane, tid, ph, /*tail*/0,
                     x, Wout, out, c1r);
        grid_sync(epoch);   // the ONLY grid sync per step
        run_layer<2>(t, par, sb, stg0, nt, mbi, wid, lane, tid, ph,
                     /*tail*/ (t < TD - 1) ? 1 : 2, x, Wout, out, c2r);
        // no sync here: L1(t+1) only reads data guaranteed by the sync above
    }
}

// ---------------- launch ----------------
extern "C" void kernel_launch(void* const* d_in, const int* in_sizes, int n_in,
                              void* d_out, int out_size)
{
    const float* x     = (const float*)d_in[0];
    const float* W_ih1 = (const float*)d_in[1];
    const float* W_hh1 = (const float*)d_in[2];
    const float* b_ih1 = (const float*)d_in[3];
    const float* b_hh1 = (const float*)d_in[4];
    const float* W_ih2 = (const float*)d_in[5];
    const float* W_hh2 = (const float*)d_in[6];
    const float* b_ih2 = (const float*)d_in[7];
    const float* b_hh2 = (const float*)d_in[8];
    const float* W_out = (const float*)d_in[9];
    const float* b_out = (const float*)d_in[10];
    float* out = (float*)d_out;

    cudaFuncSetAttribute(lstm_persist, cudaFuncAttributeMaxDynamicSharedMemorySize, SMEM_DYN);

    init_k<<<2048, 256>>>(W_ih1, W_hh1, b_ih1, b_hh1, W_ih2, W_hh2, b_ih2, b_hh2);
    lstm_persist<<<128, 256, SMEM_DYN>>>(x, W_out, b_out, out);

    (void)in_sizes; (void)n_in; (void)out_size;
}